// round 4
// baseline (speedup 1.0000x reference)
#include <cuda_runtime.h>
#include <math.h>

#define TINYF 1.17549435e-38f

// ---------------- precomputed HMM parameters (device globals) ----------------
__device__ __align__(16) float g_em[25 * 512];   // transposed match emissions [sym][m]
__device__ float g_insd[32];                     // insert/flank emission dist
__device__ __align__(16) float g_enter[512];
__device__ __align__(16) float g_mtm[512];       // mtm_p[m-1]
__device__ __align__(16) float g_i2m[512];       // i2m_p[m-1]
__device__ __align__(16) float g_dtm[512];       // dtm_p[m-1]
__device__ __align__(16) float g_m2e[512];       // m2e_tot[m]
__device__ __align__(16) float g_m2i[512];       // m2i_p[m]
__device__ __align__(16) float g_i2i[512];       // i2i_p[m]
__device__ __align__(16) float g_asc[512];       // scan mult dtd_p[m-1]
__device__ __align__(16) float g_msc[512];       // scan coeff mtd_p[m]
__device__ float g_scal[8];                      // floop,fexit,be,ep0,ep1,p0

// ---------------- setup: build all derived parameters (1 block, 512 thr) ----
__global__ void setup_kernel(
    const float* __restrict__ em_kernel, const float* __restrict__ ins_kernel,
    const float* __restrict__ flank_kernel, const float* __restrict__ btm,
    const float* __restrict__ m2e, const float* __restrict__ mtm,
    const float* __restrict__ m2i, const float* __restrict__ i2m,
    const float* __restrict__ i2i, const float* __restrict__ mtd,
    const float* __restrict__ dtm, const float* __restrict__ dtd,
    const float* __restrict__ lf_loop, const float* __restrict__ lf_exit,
    const float* __restrict__ e2u, const float* __restrict__ e2r,
    const float* __restrict__ e2t)
{
    __shared__ float red[512];
    __shared__ float incl[512];
    int m = threadIdx.x;

    // dp softmax2(dtm,dtd) at k=m-1 and k=m
    float dtmp_m1 = 0.f, dtdp_m1 = 0.f;
    if (m >= 1) {
        float a = dtm[m-1], b = dtd[m-1], mx = fmaxf(a, b);
        float ea = expf(a-mx), eb = expf(b-mx), z = ea+eb;
        dtmp_m1 = ea/z; dtdp_m1 = eb/z;
    }
    float dtdp_m = 0.f;
    if (m <= 510) {
        float a = dtm[m], b = dtd[m], mx = fmaxf(a, b);
        float ea = expf(a-mx), eb = expf(b-mx);
        dtdp_m = eb/(ea+eb);
    }
    // mp softmax4 at k=m : m2ip[m], m2ep[m], mtd_p[m+1]
    float m2ip_m = 0.f, m2ep_m = 0.f, mtdp_next = 0.f;
    if (m <= 510) {
        float v0 = mtm[m], v1 = m2i[m], v2 = m2e[m], v3 = mtd[m+1];
        float mx = fmaxf(fmaxf(v0,v1), fmaxf(v2,v3));
        float e0 = expf(v0-mx), e1 = expf(v1-mx), e2 = expf(v2-mx), e3 = expf(v3-mx);
        float z = e0+e1+e2+e3;
        m2ip_m = e1/z; m2ep_m = e2/z; mtdp_next = e3/z;
    }
    // mp softmax4 at k=m-1 : mtmp[m-1], mtd_p[m]
    float mtmp_m1 = 0.f, mtdp_m_mid = 0.f;
    if (m >= 1) {
        float v0 = mtm[m-1], v1 = m2i[m-1], v2 = m2e[m-1], v3 = mtd[m];
        float mx = fmaxf(fmaxf(v0,v1), fmaxf(v2,v3));
        float e0 = expf(v0-mx), e1 = expf(v1-mx), e2 = expf(v2-mx), e3 = expf(v3-mx);
        float z = e0+e1+e2+e3;
        mtmp_m1 = e0/z; mtdp_m_mid = e3/z;
    }
    // ip softmax2 at k=m (i2ip[m]) and k=m-1 (i2mp[m-1])
    float i2ip_m = 0.f;
    if (m <= 510) {
        float a = i2m[m], b = i2i[m], mx = fmaxf(a, b);
        float ea = expf(a-mx), eb = expf(b-mx);
        i2ip_m = eb/(ea+eb);
    }
    float i2mp_m1 = 0.f;
    if (m >= 1) {
        float a = i2m[m-1], b = i2i[m-1], mx = fmaxf(a, b);
        float ea = expf(a-mx), eb = expf(b-mx);
        i2mp_m1 = ea/(ea+eb);
    }

    // begin softmax over [btm(512), mtd[0]]
    float bx = btm[m];
    red[m] = bx; __syncthreads();
    for (int s = 256; s > 0; s >>= 1) { if (m < s) red[m] = fmaxf(red[m], red[m+s]); __syncthreads(); }
    float bmx = fmaxf(red[0], mtd[0]);
    __syncthreads();
    float bex = expf(bx - bmx);
    red[m] = bex; __syncthreads();
    for (int s = 256; s > 0; s >>= 1) { if (m < s) red[m] += red[m+s]; __syncthreads(); }
    float bz = red[0] + expf(mtd[0] - bmx);
    __syncthreads();
    float btmp_m  = bex / bz;
    float mtd_p0  = expf(mtd[0] - bmx) / bz;

    // cp prefix sum: incl[k] = sum_{i<=k} log dtd_p[i]; cp[k] = incl[k-1], cp[0]=0
    incl[m] = (m <= 510) ? logf(dtdp_m) : 0.f;
    __syncthreads();
    for (int d = 1; d < 512; d <<= 1) {
        float v = incl[m];
        float add = (m >= d) ? incl[m-d] : 0.f;
        __syncthreads();
        incl[m] = v + add;
        __syncthreads();
    }
    float cp511 = incl[510];
    float cpm1  = (m >= 2) ? incl[m-2] : 0.f;   // cp[m-1] (m>=1); m==1 -> cp[0]=0
    float cpp1  = incl[m];                       // cp[m+1] (valid m<=510)
    float be = mtd_p0 * expf(cp511);
    float enter_m = btmp_m + ((m >= 1) ? mtd_p0 * expf(cpm1) * dtmp_m1 : 0.f);
    float m2etot = (m <= 510) ? (m2ep_m + mtdp_next * expf(cp511 - cpp1)) : 1.f;
    float mtdp_m = (m == 0) ? mtd_p0 : mtdp_m_mid;

    g_enter[m] = enter_m;
    g_mtm[m]   = mtmp_m1;
    g_i2m[m]   = i2mp_m1;
    g_dtm[m]   = (m >= 1) ? dtmp_m1 : 0.f;
    g_m2e[m]   = m2etot;
    g_m2i[m]   = m2ip_m;
    g_i2i[m]   = i2ip_m;
    g_asc[m]   = (m >= 1) ? dtdp_m1 : 1.f;
    g_msc[m]   = mtdp_m;

    // match emission row m -> transposed
    {
        const float* row = em_kernel + m * 25;
        float mxr = row[0];
        for (int s = 1; s < 25; s++) mxr = fmaxf(mxr, row[s]);
        float z = 0.f;
        for (int s = 0; s < 25; s++) z += expf(row[s] - mxr);
        float invz = 1.f / z;
        for (int s = 0; s < 25; s++) g_em[s * 512 + m] = expf(row[s] - mxr) * invz;
    }
    if (m == 0) {
        float mxi = ins_kernel[0];
        for (int s = 1; s < 25; s++) mxi = fmaxf(mxi, ins_kernel[s]);
        float z = 0.f;
        for (int s = 0; s < 25; s++) z += expf(ins_kernel[s] - mxi);
        for (int s = 0; s < 25; s++) g_insd[s] = expf(ins_kernel[s] - mxi) / z;
        float a = lf_loop[0], b = lf_exit[0], mx = fmaxf(a, b);
        float ea = expf(a-mx), eb = expf(b-mx), z2 = ea+eb;
        float u = e2u[0], r = e2r[0], t = e2t[0];
        float mxe = fmaxf(fmaxf(u, r), t);
        float eu = expf(u-mxe), er = expf(r-mxe), et = expf(t-mxe);
        float ze = eu + er + et;
        g_scal[0] = ea/z2;  // floop
        g_scal[1] = eb/z2;  // fexit
        g_scal[2] = be;
        g_scal[3] = eu/ze;  // ep0
        g_scal[4] = er/ze;  // ep1
        g_scal[5] = 1.f / (1.f + expf(-flank_kernel[0]));  // p0
    }
}

// ---------------- forward kernel: 1 CTA per batch, 128 threads --------------
__global__ __launch_bounds__(128, 1)
void fwd_kernel(const int* __restrict__ seq, float* __restrict__ out)
{
    __shared__ int   s_seq[1024];
    __shared__ float s_insd[32];
    __shared__ float s_wA[4], s_wB[4], s_mx[4], s_tot[4], s_nbM[4], s_nbI[4];

    const int tid = threadIdx.x, lane = tid & 31, warp = tid >> 5;
    const int b = blockIdx.x;
    const int m0 = tid * 4;
    const unsigned FULL = 0xffffffffu;

    // stage sequence + insert dist
    {
        const int4* sp = (const int4*)(seq + b * 1024);
        ((int4*)s_seq)[tid]       = sp[tid];
        ((int4*)s_seq)[tid + 128] = sp[tid + 128];
        if (tid < 25) s_insd[tid] = g_insd[tid];
    }
    // per-thread constants
    const float4 en   = *(const float4*)(g_enter + m0);
    const float4 mtc  = *(const float4*)(g_mtm   + m0);
    const float4 i2mc = *(const float4*)(g_i2m   + m0);
    const float4 dtc  = *(const float4*)(g_dtm   + m0);
    const float4 mec  = *(const float4*)(g_m2e   + m0);
    const float4 mic  = *(const float4*)(g_m2i   + m0);
    const float4 iic  = *(const float4*)(g_i2i   + m0);
    const float4 asc  = *(const float4*)(g_asc   + m0);
    const float4 msc  = *(const float4*)(g_msc   + m0);
    const float cB0 = asc.y * asc.z * asc.w;
    const float cB1 = asc.z * asc.w;
    const float cB2 = asc.w;
    const float segA = asc.x * asc.y * asc.z * asc.w;
    const float floop = g_scal[0], fexit = g_scal[1], be = g_scal[2];
    const float ep0 = g_scal[3], ep1 = g_scal[4], p0 = g_scal[5];
    const float fbe0 = fexit * be * ep0, fbe1 = fexit * be * ep1;
    __syncthreads();

    // ---- t = 0 init (unnormalized) ----
    int c = s_seq[0];
    float eins = s_insd[c];
    float4 em = __ldg((const float4*)(g_em + c * 512 + m0));
    const float q0 = 1.f - p0;
    float nM0 = q0*en.x*em.x, nM1 = q0*en.y*em.y, nM2 = q0*en.z*em.z, nM3 = q0*en.w*em.w;
    float nI0 = 0.f, nI1 = 0.f, nI2 = 0.f, nI3 = 0.f;
    float nLF = p0 * eins, nU = q0 * be * ep0 * eins, nRF = q0 * be * ep1 * eins;

    float aM0, aM1, aM2, aM3, aI0, aI1, aI2, aI3, aLF, aU, aRF;
    float nbM = 0.f, nbI = 0.f;
    float ll = 0.f;
    {
        float tp = nM0+nM1+nM2+nM3+nI0+nI1+nI2+nI3;
        #pragma unroll
        for (int d = 16; d; d >>= 1) tp += __shfl_xor_sync(FULL, tp, d);
        if (lane == 0)  s_tot[warp] = tp;
        if (lane == 31) { s_nbM[warp] = nM3; s_nbI[warp] = nI3; }
        __syncthreads();
        float s = s_tot[0]+s_tot[1]+s_tot[2]+s_tot[3] + nLF + nU + nRF + TINYF;
        float inv = 1.f / s; ll = logf(s);
        aM0=nM0*inv; aM1=nM1*inv; aM2=nM2*inv; aM3=nM3*inv;
        aI0=nI0*inv; aI1=nI1*inv; aI2=nI2*inv; aI3=nI3*inv;
        aLF=nLF*inv; aU=nU*inv; aRF=nRF*inv;
        if (lane == 0 && warp > 0) { nbM = s_nbM[warp-1]*inv; nbI = s_nbI[warp-1]*inv; }
    }

    // ---- main recurrence ----
    for (int t = 1; t < 1024; t++) {
        c = s_seq[t];
        eins = s_insd[c];
        em = __ldg((const float4*)(g_em + c * 512 + m0));

        float prevM = __shfl_up_sync(FULL, aM3, 1);
        float prevI = __shfl_up_sync(FULL, aI3, 1);
        if (lane == 0) { prevM = nbM; prevI = nbI; }

        // scan segment: B_m = aM_m * mtd_p[m]
        float B0 = prevM * msc.x, B1 = aM0 * msc.y, B2 = aM1 * msc.z, B3 = aM2 * msc.w;
        float iB = fmaf(B0, cB0, fmaf(B1, cB1, fmaf(B2, cB2, B3)));
        float iA = segA;
        float mx = fmaf(mec.x, aM0, fmaf(mec.y, aM1, fmaf(mec.z, aM2, mec.w * aM3)));

        #pragma unroll
        for (int d = 1; d < 32; d <<= 1) {
            float pA = __shfl_up_sync(FULL, iA, d);
            float pB = __shfl_up_sync(FULL, iB, d);
            mx += __shfl_xor_sync(FULL, mx, d);
            if (lane >= d) { iB = fmaf(pB, iA, iB); iA *= pA; }
        }
        float eA = __shfl_up_sync(FULL, iA, 1);
        float eB = __shfl_up_sync(FULL, iB, 1);
        if (lane == 0) { eA = 1.f; eB = 0.f; }
        if (lane == 31) { s_wA[warp] = iA; s_wB[warp] = iB; }
        if (lane == 0)  s_mx[warp] = mx;
        __syncthreads();                       // SYNC 1

        float pB = 0.f;
        #pragma unroll
        for (int w = 0; w < 4; w++) if (w < warp) pB = fmaf(pB, s_wA[w], s_wB[w]);
        float mexit = s_mx[0] + s_mx[1] + s_mx[2] + s_mx[3];
        float w0 = fmaf(pB, eA, eB);           // W_{m0-1}
        float e1 = fmaf(w0, asc.x, B0);        // W_{m0}
        float e2 = fmaf(e1, asc.y, B1);
        float e3 = fmaf(e2, asc.z, B2);

        float fc = fexit * (aLF + aU);
        nM0 = em.x * fmaf(dtc.x, w0, fmaf(i2mc.x, prevI, fmaf(mtc.x, prevM, en.x*fc)));
        nM1 = em.y * fmaf(dtc.y, e1, fmaf(i2mc.y, aI0,   fmaf(mtc.y, aM0,   en.y*fc)));
        nM2 = em.z * fmaf(dtc.z, e2, fmaf(i2mc.z, aI1,   fmaf(mtc.z, aM1,   en.z*fc)));
        nM3 = em.w * fmaf(dtc.w, e3, fmaf(i2mc.w, aI2,   fmaf(mtc.w, aM2,   en.w*fc)));
        nI0 = eins * fmaf(mic.x, aM0, iic.x * aI0);
        nI1 = eins * fmaf(mic.y, aM1, iic.y * aI1);
        nI2 = eins * fmaf(mic.z, aM2, iic.z * aI2);
        nI3 = eins * fmaf(mic.w, aM3, iic.w * aI3);
        nLF = eins * floop * aLF;
        nU  = eins * (fmaf(ep0, mexit, fbe0 * aLF) + (floop + fbe0) * aU);
        nRF = eins * (fmaf(ep1, mexit, fbe1 * (aLF + aU)) + floop * aRF);

        float tp = nM0+nM1+nM2+nM3+nI0+nI1+nI2+nI3;
        #pragma unroll
        for (int d = 16; d; d >>= 1) tp += __shfl_xor_sync(FULL, tp, d);
        if (lane == 0)  s_tot[warp] = tp;
        if (lane == 31) { s_nbM[warp] = nM3; s_nbI[warp] = nI3; }
        __syncthreads();                       // SYNC 2

        float s = s_tot[0]+s_tot[1]+s_tot[2]+s_tot[3] + nLF + nU + nRF + TINYF;
        float inv = 1.f / s; ll += logf(s);
        aM0=nM0*inv; aM1=nM1*inv; aM2=nM2*inv; aM3=nM3*inv;
        aI0=nI0*inv; aI1=nI1*inv; aI2=nI2*inv; aI3=nI3*inv;
        aLF=nLF*inv; aU=nU*inv; aRF=nRF*inv;
        if (lane == 0 && warp > 0) { nbM = s_nbM[warp-1]*inv; nbI = s_nbI[warp-1]*inv; }
    }

    if (tid == 0) out[b] = ll;
}

extern "C" void kernel_launch(void* const* d_in, const int* in_sizes, int n_in,
                              void* d_out, int out_size)
{
    setup_kernel<<<1, 512>>>(
        (const float*)d_in[1],  (const float*)d_in[2],  (const float*)d_in[3],
        (const float*)d_in[4],  (const float*)d_in[5],  (const float*)d_in[6],
        (const float*)d_in[7],  (const float*)d_in[8],  (const float*)d_in[9],
        (const float*)d_in[10], (const float*)d_in[11], (const float*)d_in[12],
        (const float*)d_in[13], (const float*)d_in[14], (const float*)d_in[15],
        (const float*)d_in[16], (const float*)d_in[17]);
    fwd_kernel<<<128, 128>>>((const int*)d_in[0], (float*)d_out);
}

// round 5
// speedup vs baseline: 1.6777x; 1.6777x over previous
#include <cuda_runtime.h>
#include <math.h>

#define TINYF 1.17549435e-38f

// ---------------- precomputed HMM parameters (device globals) ----------------
__device__ __align__(16) float g_em[25 * 512];   // transposed match emissions [sym][m]
__device__ float g_insd[32];                     // insert/flank emission dist
__device__ __align__(16) float g_enter[512];
__device__ __align__(16) float g_mtm[512];       // mtm_p[m-1]
__device__ __align__(16) float g_i2m[512];       // i2m_p[m-1]
__device__ __align__(16) float g_dtm[512];       // dtm_p[m-1]
__device__ __align__(16) float g_m2e[512];       // m2e_tot[m]
__device__ __align__(16) float g_m2i[512];       // m2i_p[m]
__device__ __align__(16) float g_i2i[512];       // i2i_p[m]
__device__ __align__(16) float g_asc[512];       // scan mult dtd_p[m-1] (a_0 = 1)
__device__ __align__(16) float g_msc[512];       // scan coeff mtd_p[m]
__device__ float g_scal[8];                      // floop,fexit,be,ep0,ep1,p0

// ---------------- setup: build all derived parameters (1 block, 512 thr) ----
__global__ void setup_kernel(
    const float* __restrict__ em_kernel, const float* __restrict__ ins_kernel,
    const float* __restrict__ flank_kernel, const float* __restrict__ btm,
    const float* __restrict__ m2e, const float* __restrict__ mtm,
    const float* __restrict__ m2i, const float* __restrict__ i2m,
    const float* __restrict__ i2i, const float* __restrict__ mtd,
    const float* __restrict__ dtm, const float* __restrict__ dtd,
    const float* __restrict__ lf_loop, const float* __restrict__ lf_exit,
    const float* __restrict__ e2u, const float* __restrict__ e2r,
    const float* __restrict__ e2t)
{
    __shared__ float red[512];
    __shared__ float incl[512];
    int m = threadIdx.x;

    float dtmp_m1 = 0.f, dtdp_m1 = 0.f;
    if (m >= 1) {
        float a = dtm[m-1], b = dtd[m-1], mx = fmaxf(a, b);
        float ea = expf(a-mx), eb = expf(b-mx), z = ea+eb;
        dtmp_m1 = ea/z; dtdp_m1 = eb/z;
    }
    float dtdp_m = 0.f;
    if (m <= 510) {
        float a = dtm[m], b = dtd[m], mx = fmaxf(a, b);
        float ea = expf(a-mx), eb = expf(b-mx);
        dtdp_m = eb/(ea+eb);
    }
    float m2ip_m = 0.f, m2ep_m = 0.f, mtdp_next = 0.f;
    if (m <= 510) {
        float v0 = mtm[m], v1 = m2i[m], v2 = m2e[m], v3 = mtd[m+1];
        float mx = fmaxf(fmaxf(v0,v1), fmaxf(v2,v3));
        float e0 = expf(v0-mx), e1 = expf(v1-mx), e2 = expf(v2-mx), e3 = expf(v3-mx);
        float z = e0+e1+e2+e3;
        m2ip_m = e1/z; m2ep_m = e2/z; mtdp_next = e3/z;
    }
    float mtmp_m1 = 0.f, mtdp_m_mid = 0.f;
    if (m >= 1) {
        float v0 = mtm[m-1], v1 = m2i[m-1], v2 = m2e[m-1], v3 = mtd[m];
        float mx = fmaxf(fmaxf(v0,v1), fmaxf(v2,v3));
        float e0 = expf(v0-mx), e1 = expf(v1-mx), e2 = expf(v2-mx), e3 = expf(v3-mx);
        float z = e0+e1+e2+e3;
        mtmp_m1 = e0/z; mtdp_m_mid = e3/z;
    }
    float i2ip_m = 0.f;
    if (m <= 510) {
        float a = i2m[m], b = i2i[m], mx = fmaxf(a, b);
        float ea = expf(a-mx), eb = expf(b-mx);
        i2ip_m = eb/(ea+eb);
    }
    float i2mp_m1 = 0.f;
    if (m >= 1) {
        float a = i2m[m-1], b = i2i[m-1], mx = fmaxf(a, b);
        float ea = expf(a-mx), eb = expf(b-mx);
        i2mp_m1 = ea/(ea+eb);
    }

    // begin softmax over [btm(512), mtd[0]]
    float bx = btm[m];
    red[m] = bx; __syncthreads();
    for (int s = 256; s > 0; s >>= 1) { if (m < s) red[m] = fmaxf(red[m], red[m+s]); __syncthreads(); }
    float bmx = fmaxf(red[0], mtd[0]);
    __syncthreads();
    float bex = expf(bx - bmx);
    red[m] = bex; __syncthreads();
    for (int s = 256; s > 0; s >>= 1) { if (m < s) red[m] += red[m+s]; __syncthreads(); }
    float bz = red[0] + expf(mtd[0] - bmx);
    __syncthreads();
    float btmp_m  = bex / bz;
    float mtd_p0  = expf(mtd[0] - bmx) / bz;

    // cp prefix sum: incl[k] = sum_{i<=k} log dtd_p[i]
    incl[m] = (m <= 510) ? logf(dtdp_m) : 0.f;
    __syncthreads();
    for (int d = 1; d < 512; d <<= 1) {
        float v = incl[m];
        float add = (m >= d) ? incl[m-d] : 0.f;
        __syncthreads();
        incl[m] = v + add;
        __syncthreads();
    }
    float cp511 = incl[510];
    float cpm1  = (m >= 2) ? incl[m-2] : 0.f;
    float cpp1  = incl[m];
    float be = mtd_p0 * expf(cp511);
    float enter_m = btmp_m + ((m >= 1) ? mtd_p0 * expf(cpm1) * dtmp_m1 : 0.f);
    float m2etot = (m <= 510) ? (m2ep_m + mtdp_next * expf(cp511 - cpp1)) : 1.f;
    float mtdp_m = (m == 0) ? mtd_p0 : mtdp_m_mid;

    g_enter[m] = enter_m;
    g_mtm[m]   = mtmp_m1;
    g_i2m[m]   = i2mp_m1;
    g_dtm[m]   = (m >= 1) ? dtmp_m1 : 0.f;
    g_m2e[m]   = m2etot;
    g_m2i[m]   = m2ip_m;
    g_i2i[m]   = i2ip_m;
    g_asc[m]   = (m >= 1) ? dtdp_m1 : 1.f;
    g_msc[m]   = mtdp_m;

    {
        const float* row = em_kernel + m * 25;
        float mxr = row[0];
        for (int s = 1; s < 25; s++) mxr = fmaxf(mxr, row[s]);
        float z = 0.f;
        for (int s = 0; s < 25; s++) z += expf(row[s] - mxr);
        float invz = 1.f / z;
        for (int s = 0; s < 25; s++) g_em[s * 512 + m] = expf(row[s] - mxr) * invz;
    }
    if (m == 0) {
        float mxi = ins_kernel[0];
        for (int s = 1; s < 25; s++) mxi = fmaxf(mxi, ins_kernel[s]);
        float z = 0.f;
        for (int s = 0; s < 25; s++) z += expf(ins_kernel[s] - mxi);
        for (int s = 0; s < 25; s++) g_insd[s] = expf(ins_kernel[s] - mxi) / z;
        float a = lf_loop[0], b = lf_exit[0], mx = fmaxf(a, b);
        float ea = expf(a-mx), eb = expf(b-mx), z2 = ea+eb;
        float u = e2u[0], r = e2r[0], t = e2t[0];
        float mxe = fmaxf(fmaxf(u, r), t);
        float eu = expf(u-mxe), er = expf(r-mxe), et = expf(t-mxe);
        float ze = eu + er + et;
        g_scal[0] = ea/z2;  // floop
        g_scal[1] = eb/z2;  // fexit
        g_scal[2] = be;
        g_scal[3] = eu/ze;  // ep0
        g_scal[4] = er/ze;  // ep1
        g_scal[5] = 1.f / (1.f + expf(-flank_kernel[0]));  // p0
    }
}

// ---------------- forward kernel: 1 CTA per batch, 128 threads --------------
// Single barrier per step; deferred (every-16-step) renormalization.
struct Buf {
    float wA[4], wB[4], mx[4], tot[4];
    float nbM[8], nbI[8];
};

__global__ __launch_bounds__(128, 1)
void fwd_kernel(const int* __restrict__ seq, float* __restrict__ out)
{
    __shared__ int   s_seq[1024];
    __shared__ float s_insd[32];
    __shared__ Buf   s_b[2];
    __shared__ float s_ftot[4];

    const int tid = threadIdx.x, lane = tid & 31, warp = tid >> 5;
    const int b = blockIdx.x;
    const int m0 = tid * 4;
    const unsigned FULL = 0xffffffffu;

    // stage sequence + insert dist + nb boundary zeros
    {
        const int4* sp = (const int4*)(seq + b * 1024);
        ((int4*)s_seq)[tid]       = sp[tid];
        ((int4*)s_seq)[tid + 128] = sp[tid + 128];
        if (tid < 25) s_insd[tid] = g_insd[tid];
        if (tid < 2) { s_b[tid].nbM[0] = 0.f; s_b[tid].nbI[0] = 0.f; }
    }
    // per-thread constants
    const float4 en   = *(const float4*)(g_enter + m0);
    const float4 mtc  = *(const float4*)(g_mtm   + m0);
    const float4 i2mc = *(const float4*)(g_i2m   + m0);
    const float4 dtc  = *(const float4*)(g_dtm   + m0);
    const float4 mec  = *(const float4*)(g_m2e   + m0);
    const float4 mic  = *(const float4*)(g_m2i   + m0);
    const float4 iic  = *(const float4*)(g_i2i   + m0);
    const float4 asc  = *(const float4*)(g_asc   + m0);
    const float4 msc  = *(const float4*)(g_msc   + m0);
    const float cB0 = asc.y * asc.z * asc.w;
    const float cB1 = asc.z * asc.w;
    const float cB2 = asc.w;
    const float segA = asc.x * asc.y * asc.z * asc.w;
    const float floop = g_scal[0], fexit = g_scal[1], be = g_scal[2];
    const float ep0 = g_scal[3], ep1 = g_scal[4], p0 = g_scal[5];
    const float fbe0 = fexit * be * ep0, fbe1 = fexit * be * ep1;
    // per-warp boundary propagation constants K_w = msc[128w] / asc[128w]
    float Kc0 = g_msc[0]   / g_asc[0];
    float Kc1 = g_msc[128] / g_asc[128];
    float Kc2 = g_msc[256] / g_asc[256];
    float Kc3 = g_msc[384] / g_asc[384];
    const float Kown = (warp == 0) ? Kc0 : (warp == 1) ? Kc1 : (warp == 2) ? Kc2 : Kc3;
    __syncthreads();

    // ---- t = 0 init: compute unnormalized, then one full normalize ----
    int c = s_seq[0];
    float eins = s_insd[c];
    float4 em = __ldg((const float4*)(g_em + c * 512 + m0));
    const float q0 = 1.f - p0;
    float aM0 = q0*en.x*em.x, aM1 = q0*en.y*em.y, aM2 = q0*en.z*em.z, aM3 = q0*en.w*em.w;
    float aI0 = 0.f, aI1 = 0.f, aI2 = 0.f, aI3 = 0.f;
    float aLF = p0 * eins, aU = q0 * be * ep0 * eins, aRF = q0 * be * ep1 * eins;
    float ll;
    {
        float tp = aM0+aM1+aM2+aM3;
        #pragma unroll
        for (int d = 16; d; d >>= 1) tp += __shfl_xor_sync(FULL, tp, d);
        if (lane == 0) s_ftot[warp] = tp;
        __syncthreads();
        float s = s_ftot[0]+s_ftot[1]+s_ftot[2]+s_ftot[3] + aLF + aU + aRF + TINYF;
        float inv = 1.f / s; ll = logf(s);
        aM0*=inv; aM1*=inv; aM2*=inv; aM3*=inv;
        aLF*=inv; aU*=inv; aRF*=inv;
        __syncthreads();
    }

    // ---- main recurrence: 1 barrier per step, rescale every 16 steps ----
    #pragma unroll 2
    for (int t = 1; t < 1024; t++) {
        Buf* bf = &s_b[t & 1];
        const bool rescale = ((t & 15) == 0);

        c = s_seq[t];
        eins = s_insd[c];
        em = __ldg((const float4*)(g_em + c * 512 + m0));

        // ---- phase A (intra-warp only) ----
        float prevM = __shfl_up_sync(FULL, aM3, 1);
        float prevI = __shfl_up_sync(FULL, aI3, 1);
        if (lane == 0) { prevM = 0.f; prevI = 0.f; }   // fixed post-barrier

        float B0 = prevM * msc.x, B1 = aM0 * msc.y, B2 = aM1 * msc.z, B3 = aM2 * msc.w;
        float iB = fmaf(B0, cB0, fmaf(B1, cB1, fmaf(B2, cB2, B3)));
        float iA = segA;
        float mx = fmaf(mec.x, aM0, fmaf(mec.y, aM1, fmaf(mec.z, aM2, mec.w * aM3)));

        #pragma unroll
        for (int d = 1; d < 32; d <<= 1) {
            float pA = __shfl_up_sync(FULL, iA, d);
            float pBs = __shfl_up_sync(FULL, iB, d);
            mx += __shfl_xor_sync(FULL, mx, d);
            if (lane >= d) { iB = fmaf(pBs, iA, iB); iA *= pA; }
        }
        float eA = __shfl_up_sync(FULL, iA, 1);
        float eB = __shfl_up_sync(FULL, iB, 1);
        if (lane == 0) { eA = 1.f; eB = 0.f; }

        float tp = 0.f;
        if (rescale) {
            tp = aM0+aM1+aM2+aM3+aI0+aI1+aI2+aI3;
            #pragma unroll
            for (int d = 16; d; d >>= 1) tp += __shfl_xor_sync(FULL, tp, d);
        }

        if (lane == 31) {
            bf->wA[warp] = iA; bf->wB[warp] = iB;
            bf->nbM[warp + 1] = aM3; bf->nbI[warp + 1] = aI3;
        }
        if (lane == 0) {
            bf->mx[warp] = mx;
            if (rescale) bf->tot[warp] = tp;
        }
        __syncthreads();   // the single barrier

        // ---- phase B: cross-warp combine + state update ----
        float cc = 0.f;
        if (warp > 0) {
            float Af = bf->wA[0];
            cc = fmaf(bf->nbM[0] * Kc0, Af, bf->wB[0]);
            if (warp > 1) {
                Af = bf->wA[1];
                float Bf = fmaf(bf->nbM[1] * Kc1, Af, bf->wB[1]);
                cc = fmaf(cc, Af, Bf);
                if (warp > 2) {
                    Af = bf->wA[2];
                    Bf = fmaf(bf->nbM[2] * Kc2, Af, bf->wB[2]);
                    cc = fmaf(cc, Af, Bf);
                }
            }
        }
        const float pB = cc;                       // W at end of previous warp
        const float nbOwn = bf->nbM[warp];         // neighbor warp's last aM3
        if (lane == 0) { prevM = nbOwn; prevI = bf->nbI[warp]; }

        float w0aug = fmaf(eA, fmaf(nbOwn, Kown, pB), eB);
        float wtrue = (lane == 0) ? pB : w0aug;
        float e1 = fmaf(w0aug, asc.x, B0);
        float e2 = fmaf(e1, asc.y, B1);
        float e3 = fmaf(e2, asc.z, B2);

        float mexit = (bf->mx[0] + bf->mx[1]) + (bf->mx[2] + bf->mx[3]);
        float fc = fexit * (aLF + aU);

        float nM0 = em.x * fmaf(dtc.x, wtrue, fmaf(i2mc.x, prevI, fmaf(mtc.x, prevM, en.x*fc)));
        float nM1 = em.y * fmaf(dtc.y, e1,    fmaf(i2mc.y, aI0,   fmaf(mtc.y, aM0,   en.y*fc)));
        float nM2 = em.z * fmaf(dtc.z, e2,    fmaf(i2mc.z, aI1,   fmaf(mtc.z, aM1,   en.z*fc)));
        float nM3 = em.w * fmaf(dtc.w, e3,    fmaf(i2mc.w, aI2,   fmaf(mtc.w, aM2,   en.w*fc)));
        float nI0 = eins * fmaf(mic.x, aM0, iic.x * aI0);
        float nI1 = eins * fmaf(mic.y, aM1, iic.y * aI1);
        float nI2 = eins * fmaf(mic.z, aM2, iic.z * aI2);
        float nI3 = eins * fmaf(mic.w, aM3, iic.w * aI3);
        float nLF = eins * floop * aLF;
        float nU  = eins * (fmaf(ep0, mexit, fbe0 * aLF) + (floop + fbe0) * aU);
        float nRF = eins * (fmaf(ep1, mexit, fbe1 * (aLF + aU)) + floop * aRF);

        if (rescale) {
            float s = (bf->tot[0] + bf->tot[1]) + (bf->tot[2] + bf->tot[3])
                    + aLF + aU + aRF + TINYF;
            float inv = 1.f / s;
            ll += logf(s);
            nM0*=inv; nM1*=inv; nM2*=inv; nM3*=inv;
            nI0*=inv; nI1*=inv; nI2*=inv; nI3*=inv;
            nLF*=inv; nU*=inv; nRF*=inv;
        }

        aM0=nM0; aM1=nM1; aM2=nM2; aM3=nM3;
        aI0=nI0; aI1=nI1; aI2=nI2; aI3=nI3;
        aLF=nLF; aU=nU; aRF=nRF;
    }

    // ---- final mass -> log-likelihood ----
    {
        float tp = aM0+aM1+aM2+aM3+aI0+aI1+aI2+aI3;
        #pragma unroll
        for (int d = 16; d; d >>= 1) tp += __shfl_xor_sync(FULL, tp, d);
        __syncthreads();
        if (lane == 0) s_ftot[warp] = tp;
        __syncthreads();
        float s = s_ftot[0]+s_ftot[1]+s_ftot[2]+s_ftot[3] + aLF + aU + aRF + TINYF;
        ll += logf(s);
        if (tid == 0) out[b] = ll;
    }
}

extern "C" void kernel_launch(void* const* d_in, const int* in_sizes, int n_in,
                              void* d_out, int out_size)
{
    setup_kernel<<<1, 512>>>(
        (const float*)d_in[1],  (const float*)d_in[2],  (const float*)d_in[3],
        (const float*)d_in[4],  (const float*)d_in[5],  (const float*)d_in[6],
        (const float*)d_in[7],  (const float*)d_in[8],  (const float*)d_in[9],
        (const float*)d_in[10], (const float*)d_in[11], (const float*)d_in[12],
        (const float*)d_in[13], (const float*)d_in[14], (const float*)d_in[15],
        (const float*)d_in[16], (const float*)d_in[17]);
    fwd_kernel<<<128, 128>>>((const int*)d_in[0], (float*)d_out);
}

// round 6
// speedup vs baseline: 1.7721x; 1.0562x over previous
#include <cuda_runtime.h>
#include <math.h>

#define TINYF 1.17549435e-38f

// ---------------- precomputed HMM parameters (device globals) ----------------
__device__ __align__(16) float g_em[25 * 512];   // transposed match emissions [sym][m]
__device__ float g_insd[32];                     // insert/flank emission dist
__device__ __align__(16) float g_enter[512];
__device__ __align__(16) float g_mtm[512];       // mtm_p[m-1]
__device__ __align__(16) float g_i2m[512];       // i2m_p[m-1]
__device__ __align__(16) float g_dtm[512];       // dtm_p[m-1]
__device__ __align__(16) float g_m2e[512];       // m2e_tot[m]
__device__ __align__(16) float g_m2i[512];       // m2i_p[m]
__device__ __align__(16) float g_i2i[512];       // i2i_p[m]
__device__ __align__(16) float g_asc[512];       // scan mult dtd_p[m-1] (a_0 = 1)
__device__ __align__(16) float g_msc[512];       // scan coeff mtd_p[m]
__device__ float g_scal[8];                      // floop,fexit,be,ep0,ep1,p0

// ---------------- setup: build all derived parameters (1 block, 512 thr) ----
__global__ void setup_kernel(
    const float* __restrict__ em_kernel, const float* __restrict__ ins_kernel,
    const float* __restrict__ flank_kernel, const float* __restrict__ btm,
    const float* __restrict__ m2e, const float* __restrict__ mtm,
    const float* __restrict__ m2i, const float* __restrict__ i2m,
    const float* __restrict__ i2i, const float* __restrict__ mtd,
    const float* __restrict__ dtm, const float* __restrict__ dtd,
    const float* __restrict__ lf_loop, const float* __restrict__ lf_exit,
    const float* __restrict__ e2u, const float* __restrict__ e2r,
    const float* __restrict__ e2t)
{
    __shared__ float red[512];
    __shared__ float incl[512];
    int m = threadIdx.x;

    float dtmp_m1 = 0.f, dtdp_m1 = 0.f;
    if (m >= 1) {
        float a = dtm[m-1], b = dtd[m-1], mx = fmaxf(a, b);
        float ea = expf(a-mx), eb = expf(b-mx), z = ea+eb;
        dtmp_m1 = ea/z; dtdp_m1 = eb/z;
    }
    float dtdp_m = 0.f;
    if (m <= 510) {
        float a = dtm[m], b = dtd[m], mx = fmaxf(a, b);
        float ea = expf(a-mx), eb = expf(b-mx);
        dtdp_m = eb/(ea+eb);
    }
    float m2ip_m = 0.f, m2ep_m = 0.f, mtdp_next = 0.f;
    if (m <= 510) {
        float v0 = mtm[m], v1 = m2i[m], v2 = m2e[m], v3 = mtd[m+1];
        float mx = fmaxf(fmaxf(v0,v1), fmaxf(v2,v3));
        float e0 = expf(v0-mx), e1 = expf(v1-mx), e2 = expf(v2-mx), e3 = expf(v3-mx);
        float z = e0+e1+e2+e3;
        m2ip_m = e1/z; m2ep_m = e2/z; mtdp_next = e3/z;
    }
    float mtmp_m1 = 0.f, mtdp_m_mid = 0.f;
    if (m >= 1) {
        float v0 = mtm[m-1], v1 = m2i[m-1], v2 = m2e[m-1], v3 = mtd[m];
        float mx = fmaxf(fmaxf(v0,v1), fmaxf(v2,v3));
        float e0 = expf(v0-mx), e1 = expf(v1-mx), e2 = expf(v2-mx), e3 = expf(v3-mx);
        float z = e0+e1+e2+e3;
        mtmp_m1 = e0/z; mtdp_m_mid = e3/z;
    }
    float i2ip_m = 0.f;
    if (m <= 510) {
        float a = i2m[m], b = i2i[m], mx = fmaxf(a, b);
        float ea = expf(a-mx), eb = expf(b-mx);
        i2ip_m = eb/(ea+eb);
    }
    float i2mp_m1 = 0.f;
    if (m >= 1) {
        float a = i2m[m-1], b = i2i[m-1], mx = fmaxf(a, b);
        float ea = expf(a-mx), eb = expf(b-mx);
        i2mp_m1 = ea/(ea+eb);
    }

    // begin softmax over [btm(512), mtd[0]]
    float bx = btm[m];
    red[m] = bx; __syncthreads();
    for (int s = 256; s > 0; s >>= 1) { if (m < s) red[m] = fmaxf(red[m], red[m+s]); __syncthreads(); }
    float bmx = fmaxf(red[0], mtd[0]);
    __syncthreads();
    float bex = expf(bx - bmx);
    red[m] = bex; __syncthreads();
    for (int s = 256; s > 0; s >>= 1) { if (m < s) red[m] += red[m+s]; __syncthreads(); }
    float bz = red[0] + expf(mtd[0] - bmx);
    __syncthreads();
    float btmp_m  = bex / bz;
    float mtd_p0  = expf(mtd[0] - bmx) / bz;

    // cp prefix sum
    incl[m] = (m <= 510) ? logf(dtdp_m) : 0.f;
    __syncthreads();
    for (int d = 1; d < 512; d <<= 1) {
        float v = incl[m];
        float add = (m >= d) ? incl[m-d] : 0.f;
        __syncthreads();
        incl[m] = v + add;
        __syncthreads();
    }
    float cp511 = incl[510];
    float cpm1  = (m >= 2) ? incl[m-2] : 0.f;
    float cpp1  = incl[m];
    float be = mtd_p0 * expf(cp511);
    float enter_m = btmp_m + ((m >= 1) ? mtd_p0 * expf(cpm1) * dtmp_m1 : 0.f);
    float m2etot = (m <= 510) ? (m2ep_m + mtdp_next * expf(cp511 - cpp1)) : 1.f;
    float mtdp_m = (m == 0) ? mtd_p0 : mtdp_m_mid;

    g_enter[m] = enter_m;
    g_mtm[m]   = mtmp_m1;
    g_i2m[m]   = i2mp_m1;
    g_dtm[m]   = (m >= 1) ? dtmp_m1 : 0.f;
    g_m2e[m]   = m2etot;
    g_m2i[m]   = m2ip_m;
    g_i2i[m]   = i2ip_m;
    g_asc[m]   = (m >= 1) ? dtdp_m1 : 1.f;
    g_msc[m]   = mtdp_m;

    {
        const float* row = em_kernel + m * 25;
        float mxr = row[0];
        for (int s = 1; s < 25; s++) mxr = fmaxf(mxr, row[s]);
        float z = 0.f;
        for (int s = 0; s < 25; s++) z += expf(row[s] - mxr);
        float invz = 1.f / z;
        for (int s = 0; s < 25; s++) g_em[s * 512 + m] = expf(row[s] - mxr) * invz;
    }
    if (m == 0) {
        float mxi = ins_kernel[0];
        for (int s = 1; s < 25; s++) mxi = fmaxf(mxi, ins_kernel[s]);
        float z = 0.f;
        for (int s = 0; s < 25; s++) z += expf(ins_kernel[s] - mxi);
        for (int s = 0; s < 25; s++) g_insd[s] = expf(ins_kernel[s] - mxi) / z;
        float a = lf_loop[0], b = lf_exit[0], mx = fmaxf(a, b);
        float ea = expf(a-mx), eb = expf(b-mx), z2 = ea+eb;
        float u = e2u[0], r = e2r[0], t = e2t[0];
        float mxe = fmaxf(fmaxf(u, r), t);
        float eu = expf(u-mxe), er = expf(r-mxe), et = expf(t-mxe);
        float ze = eu + er + et;
        g_scal[0] = ea/z2;  // floop
        g_scal[1] = eb/z2;  // fexit
        g_scal[2] = be;
        g_scal[3] = eu/ze;  // ep0
        g_scal[4] = er/ze;  // ep1
        g_scal[5] = 1.f / (1.f + expf(-flank_kernel[0]));  // p0
    }
}

// ---------------- forward kernel: 1 CTA per batch, 64 threads, 2 warps ------
struct Buf {
    float wB[2], mx[2], tot[2];
    float nbM[3], nbI[3];
};

__global__ __launch_bounds__(64, 1)
void fwd_kernel(const int* __restrict__ seq, float* __restrict__ out)
{
    __shared__ int   s_seq[1024];
    __shared__ float s_insd[32];
    __shared__ Buf   s_b[2];
    __shared__ float s_ftot[2];

    const int tid = threadIdx.x, lane = tid & 31, warp = tid >> 5;
    const int b = blockIdx.x;
    const int m0 = tid * 8;
    const unsigned FULL = 0xffffffffu;

    // stage sequence + insert dist + boundary zeros
    {
        const int4* sp = (const int4*)(seq + b * 1024);
        #pragma unroll
        for (int k = 0; k < 4; k++)
            ((int4*)s_seq)[tid + 64 * k] = sp[tid + 64 * k];
        if (tid < 25) s_insd[tid] = g_insd[tid];
        if (tid < 2) { s_b[tid].nbM[0] = 0.f; s_b[tid].nbI[0] = 0.f; }
    }

    // per-thread constants (8 states each)
    float en[8], mtc[8], i2mc[8], dtc[8], mec[8], mic[8], iic[8], asc[8], msc[8];
    {
        #pragma unroll
        for (int h = 0; h < 2; h++) {
            int o = m0 + 4 * h;
            float4 v;
            v = *(const float4*)(g_enter + o); en[4*h]=v.x; en[4*h+1]=v.y; en[4*h+2]=v.z; en[4*h+3]=v.w;
            v = *(const float4*)(g_mtm   + o); mtc[4*h]=v.x; mtc[4*h+1]=v.y; mtc[4*h+2]=v.z; mtc[4*h+3]=v.w;
            v = *(const float4*)(g_i2m   + o); i2mc[4*h]=v.x; i2mc[4*h+1]=v.y; i2mc[4*h+2]=v.z; i2mc[4*h+3]=v.w;
            v = *(const float4*)(g_dtm   + o); dtc[4*h]=v.x; dtc[4*h+1]=v.y; dtc[4*h+2]=v.z; dtc[4*h+3]=v.w;
            v = *(const float4*)(g_m2e   + o); mec[4*h]=v.x; mec[4*h+1]=v.y; mec[4*h+2]=v.z; mec[4*h+3]=v.w;
            v = *(const float4*)(g_m2i   + o); mic[4*h]=v.x; mic[4*h+1]=v.y; mic[4*h+2]=v.z; mic[4*h+3]=v.w;
            v = *(const float4*)(g_i2i   + o); iic[4*h]=v.x; iic[4*h+1]=v.y; iic[4*h+2]=v.z; iic[4*h+3]=v.w;
            v = *(const float4*)(g_asc   + o); asc[4*h]=v.x; asc[4*h+1]=v.y; asc[4*h+2]=v.z; asc[4*h+3]=v.w;
            v = *(const float4*)(g_msc   + o); msc[4*h]=v.x; msc[4*h+1]=v.y; msc[4*h+2]=v.z; msc[4*h+3]=v.w;
        }
    }
    // suffix products for segment dot: cB[k] = prod asc[k+1..7]
    float cB[8];
    cB[7] = 1.f;
    #pragma unroll
    for (int k = 6; k >= 0; k--) cB[k] = asc[k+1] * cB[k+1];
    const float segA = asc[0] * cB[0];

    const float floop = g_scal[0], fexit = g_scal[1], be = g_scal[2];
    const float ep0 = g_scal[3], ep1 = g_scal[4], p0 = g_scal[5];
    const float fbe0 = fexit * be * ep0, fbe1 = fexit * be * ep1;
    const float Kown = (warp == 1) ? (g_msc[256] / g_asc[256]) : 0.f;

    // prolog: time-invariant scan multipliers (A-side constants)
    float cS[5], eAc;
    {
        float iA = segA;
        #pragma unroll
        for (int l = 0, d = 1; d < 32; d <<= 1, l++) {
            float p = __shfl_up_sync(FULL, iA, d);
            cS[l] = (lane >= d) ? iA : 0.f;
            if (lane >= d) iA *= p;
        }
        eAc = __shfl_up_sync(FULL, iA, 1);
        if (lane == 0) eAc = 1.f;
    }
    __syncthreads();

    // ---- t = 0 init ----
    int c = s_seq[0];
    float eins = s_insd[c];
    float aM[8], aI[8], em[8];
    {
        float4 ea = __ldg((const float4*)(g_em + c * 512 + m0));
        float4 eb = __ldg((const float4*)(g_em + c * 512 + m0 + 4));
        em[0]=ea.x; em[1]=ea.y; em[2]=ea.z; em[3]=ea.w;
        em[4]=eb.x; em[5]=eb.y; em[6]=eb.z; em[7]=eb.w;
    }
    const float q0 = 1.f - p0;
    #pragma unroll
    for (int k = 0; k < 8; k++) { aM[k] = q0 * en[k] * em[k]; aI[k] = 0.f; }
    float aLF = p0 * eins, aU = q0 * be * ep0 * eins, aRF = q0 * be * ep1 * eins;
    float ll;
    {
        float tp = 0.f;
        #pragma unroll
        for (int k = 0; k < 8; k++) tp += aM[k];
        #pragma unroll
        for (int d = 16; d; d >>= 1) tp += __shfl_xor_sync(FULL, tp, d);
        if (lane == 0) s_ftot[warp] = tp;
        __syncthreads();
        float s = s_ftot[0] + s_ftot[1] + aLF + aU + aRF + TINYF;
        float inv = 1.f / s; ll = logf(s);
        #pragma unroll
        for (int k = 0; k < 8; k++) aM[k] *= inv;
        aLF *= inv; aU *= inv; aRF *= inv;
        __syncthreads();
    }

    // ---- main recurrence: 1 barrier per step, rescale every 16 steps ----
    #pragma unroll 2
    for (int t = 1; t < 1024; t++) {
        Buf* bf = &s_b[t & 1];
        const bool rescale = ((t & 15) == 0);

        c = s_seq[t];
        eins = s_insd[c];
        {
            float4 ea = __ldg((const float4*)(g_em + c * 512 + m0));
            float4 eb = __ldg((const float4*)(g_em + c * 512 + m0 + 4));
            em[0]=ea.x; em[1]=ea.y; em[2]=ea.z; em[3]=ea.w;
            em[4]=eb.x; em[5]=eb.y; em[6]=eb.z; em[7]=eb.w;
        }

        // ---- phase A (intra-warp) ----
        float prevM = __shfl_up_sync(FULL, aM[7], 1);
        float prevI = __shfl_up_sync(FULL, aI[7], 1);
        if (lane == 0) { prevM = 0.f; prevI = 0.f; }

        float B[8];
        B[0] = prevM * msc[0];
        #pragma unroll
        for (int k = 1; k < 8; k++) B[k] = aM[k-1] * msc[k];

        float iB = 0.f, mx = 0.f;
        #pragma unroll
        for (int k = 0; k < 8; k++) {
            iB = fmaf(B[k], cB[k], iB);
            mx = fmaf(mec[k], aM[k], mx);
        }

        #pragma unroll
        for (int l = 0, d = 1; d < 32; d <<= 1, l++) {
            float pBs = __shfl_up_sync(FULL, iB, d);
            mx += __shfl_xor_sync(FULL, mx, d);
            iB = fmaf(pBs, cS[l], iB);
        }
        float eB = __shfl_up_sync(FULL, iB, 1);
        if (lane == 0) eB = 0.f;

        float tp = 0.f;
        if (rescale) {
            #pragma unroll
            for (int k = 0; k < 8; k++) tp += aM[k] + aI[k];
            #pragma unroll
            for (int d = 16; d; d >>= 1) tp += __shfl_xor_sync(FULL, tp, d);
        }

        if (lane == 31) {
            bf->wB[warp] = iB;
            bf->nbM[warp + 1] = aM[7]; bf->nbI[warp + 1] = aI[7];
        }
        if (lane == 0) {
            bf->mx[warp] = mx;
            if (rescale) bf->tot[warp] = tp;
        }
        __syncthreads();   // the single barrier

        // ---- phase B: cross-warp combine + state update ----
        const float pB = (warp == 1) ? bf->wB[0] : 0.f;
        const float nbOwn = bf->nbM[warp];
        if (lane == 0) { prevM = nbOwn; prevI = bf->nbI[warp]; }

        float w0aug = fmaf(eAc, fmaf(nbOwn, Kown, pB), eB);
        float wtrue = (lane == 0) ? pB : w0aug;

        float mexit = bf->mx[0] + bf->mx[1];
        float fc = fexit * (aLF + aU);

        float nM[8], nI[8];
        nM[0] = em[0] * fmaf(dtc[0], wtrue,
                      fmaf(i2mc[0], prevI, fmaf(mtc[0], prevM, en[0]*fc)));
        float e = w0aug;
        #pragma unroll
        for (int k = 1; k < 8; k++) {
            e = fmaf(e, asc[k-1], B[k-1]);
            nM[k] = em[k] * fmaf(dtc[k], e,
                         fmaf(i2mc[k], aI[k-1], fmaf(mtc[k], aM[k-1], en[k]*fc)));
        }
        #pragma unroll
        for (int k = 0; k < 8; k++)
            nI[k] = eins * fmaf(mic[k], aM[k], iic[k] * aI[k]);

        float nLF = eins * floop * aLF;
        float nU  = eins * (fmaf(ep0, mexit, fbe0 * aLF) + (floop + fbe0) * aU);
        float nRF = eins * (fmaf(ep1, mexit, fbe1 * (aLF + aU)) + floop * aRF);

        if (rescale) {
            float s = bf->tot[0] + bf->tot[1] + aLF + aU + aRF + TINYF;
            float inv = 1.f / s;
            ll += logf(s);
            #pragma unroll
            for (int k = 0; k < 8; k++) { nM[k] *= inv; nI[k] *= inv; }
            nLF *= inv; nU *= inv; nRF *= inv;
        }

        #pragma unroll
        for (int k = 0; k < 8; k++) { aM[k] = nM[k]; aI[k] = nI[k]; }
        aLF = nLF; aU = nU; aRF = nRF;
    }

    // ---- final mass -> log-likelihood ----
    {
        float tp = 0.f;
        #pragma unroll
        for (int k = 0; k < 8; k++) tp += aM[k] + aI[k];
        #pragma unroll
        for (int d = 16; d; d >>= 1) tp += __shfl_xor_sync(FULL, tp, d);
        __syncthreads();
        if (lane == 0) s_ftot[warp] = tp;
        __syncthreads();
        float s = s_ftot[0] + s_ftot[1] + aLF + aU + aRF + TINYF;
        ll += logf(s);
        if (tid == 0) out[b] = ll;
    }
}

extern "C" void kernel_launch(void* const* d_in, const int* in_sizes, int n_in,
                              void* d_out, int out_size)
{
    setup_kernel<<<1, 512>>>(
        (const float*)d_in[1],  (const float*)d_in[2],  (const float*)d_in[3],
        (const float*)d_in[4],  (const float*)d_in[5],  (const float*)d_in[6],
        (const float*)d_in[7],  (const float*)d_in[8],  (const float*)d_in[9],
        (const float*)d_in[10], (const float*)d_in[11], (const float*)d_in[12],
        (const float*)d_in[13], (const float*)d_in[14], (const float*)d_in[15],
        (const float*)d_in[16], (const float*)d_in[17]);
    fwd_kernel<<<128, 64>>>((const int*)d_in[0], (float*)d_out);
}

// round 7
// speedup vs baseline: 2.0248x; 1.1426x over previous
#include <cuda_runtime.h>
#include <math.h>

#define TINYF 1.17549435e-38f

// ---------------- precomputed HMM parameters (device globals) ----------------
__device__ __align__(16) float g_em[25 * 512];   // transposed match emissions [sym][m]
__device__ float g_insd[32];                     // insert/flank emission dist
__device__ __align__(16) float g_enter[512];
__device__ __align__(16) float g_mtm[512];       // mtm_p[m-1]
__device__ __align__(16) float g_i2m[512];       // i2m_p[m-1]
__device__ __align__(16) float g_dtm[512];       // dtm_p[m-1]
__device__ __align__(16) float g_m2e[512];       // m2e_tot[m]
__device__ __align__(16) float g_m2i[512];       // m2i_p[m]
__device__ __align__(16) float g_i2i[512];       // i2i_p[m]
__device__ __align__(16) float g_asc[512];       // scan mult dtd_p[m-1] (a_0 = 1)
__device__ __align__(16) float g_msc[512];       // scan coeff mtd_p[m]
__device__ float g_scal[8];                      // floop,fexit,be,ep0,ep1,p0

// ---------------- setup: build all derived parameters (1 block, 512 thr) ----
__global__ void setup_kernel(
    const float* __restrict__ em_kernel, const float* __restrict__ ins_kernel,
    const float* __restrict__ flank_kernel, const float* __restrict__ btm,
    const float* __restrict__ m2e, const float* __restrict__ mtm,
    const float* __restrict__ m2i, const float* __restrict__ i2m,
    const float* __restrict__ i2i, const float* __restrict__ mtd,
    const float* __restrict__ dtm, const float* __restrict__ dtd,
    const float* __restrict__ lf_loop, const float* __restrict__ lf_exit,
    const float* __restrict__ e2u, const float* __restrict__ e2r,
    const float* __restrict__ e2t)
{
    __shared__ float red[512];
    __shared__ float incl[512];
    int m = threadIdx.x;

    float dtmp_m1 = 0.f, dtdp_m1 = 0.f;
    if (m >= 1) {
        float a = dtm[m-1], b = dtd[m-1], mx = fmaxf(a, b);
        float ea = expf(a-mx), eb = expf(b-mx), z = ea+eb;
        dtmp_m1 = ea/z; dtdp_m1 = eb/z;
    }
    float dtdp_m = 0.f;
    if (m <= 510) {
        float a = dtm[m], b = dtd[m], mx = fmaxf(a, b);
        float ea = expf(a-mx), eb = expf(b-mx);
        dtdp_m = eb/(ea+eb);
    }
    float m2ip_m = 0.f, m2ep_m = 0.f, mtdp_next = 0.f;
    if (m <= 510) {
        float v0 = mtm[m], v1 = m2i[m], v2 = m2e[m], v3 = mtd[m+1];
        float mx = fmaxf(fmaxf(v0,v1), fmaxf(v2,v3));
        float e0 = expf(v0-mx), e1 = expf(v1-mx), e2 = expf(v2-mx), e3 = expf(v3-mx);
        float z = e0+e1+e2+e3;
        m2ip_m = e1/z; m2ep_m = e2/z; mtdp_next = e3/z;
    }
    float mtmp_m1 = 0.f, mtdp_m_mid = 0.f;
    if (m >= 1) {
        float v0 = mtm[m-1], v1 = m2i[m-1], v2 = m2e[m-1], v3 = mtd[m];
        float mx = fmaxf(fmaxf(v0,v1), fmaxf(v2,v3));
        float e0 = expf(v0-mx), e1 = expf(v1-mx), e2 = expf(v2-mx), e3 = expf(v3-mx);
        float z = e0+e1+e2+e3;
        mtmp_m1 = e0/z; mtdp_m_mid = e3/z;
    }
    float i2ip_m = 0.f;
    if (m <= 510) {
        float a = i2m[m], b = i2i[m], mx = fmaxf(a, b);
        float ea = expf(a-mx), eb = expf(b-mx);
        i2ip_m = eb/(ea+eb);
    }
    float i2mp_m1 = 0.f;
    if (m >= 1) {
        float a = i2m[m-1], b = i2i[m-1], mx = fmaxf(a, b);
        float ea = expf(a-mx), eb = expf(b-mx);
        i2mp_m1 = ea/(ea+eb);
    }

    // begin softmax over [btm(512), mtd[0]]
    float bx = btm[m];
    red[m] = bx; __syncthreads();
    for (int s = 256; s > 0; s >>= 1) { if (m < s) red[m] = fmaxf(red[m], red[m+s]); __syncthreads(); }
    float bmx = fmaxf(red[0], mtd[0]);
    __syncthreads();
    float bex = expf(bx - bmx);
    red[m] = bex; __syncthreads();
    for (int s = 256; s > 0; s >>= 1) { if (m < s) red[m] += red[m+s]; __syncthreads(); }
    float bz = red[0] + expf(mtd[0] - bmx);
    __syncthreads();
    float btmp_m  = bex / bz;
    float mtd_p0  = expf(mtd[0] - bmx) / bz;

    // cp prefix sum
    incl[m] = (m <= 510) ? logf(dtdp_m) : 0.f;
    __syncthreads();
    for (int d = 1; d < 512; d <<= 1) {
        float v = incl[m];
        float add = (m >= d) ? incl[m-d] : 0.f;
        __syncthreads();
        incl[m] = v + add;
        __syncthreads();
    }
    float cp511 = incl[510];
    float cpm1  = (m >= 2) ? incl[m-2] : 0.f;
    float cpp1  = incl[m];
    float be = mtd_p0 * expf(cp511);
    float enter_m = btmp_m + ((m >= 1) ? mtd_p0 * expf(cpm1) * dtmp_m1 : 0.f);
    float m2etot = (m <= 510) ? (m2ep_m + mtdp_next * expf(cp511 - cpp1)) : 1.f;
    float mtdp_m = (m == 0) ? mtd_p0 : mtdp_m_mid;

    g_enter[m] = enter_m;
    g_mtm[m]   = mtmp_m1;
    g_i2m[m]   = i2mp_m1;
    g_dtm[m]   = (m >= 1) ? dtmp_m1 : 0.f;
    g_m2e[m]   = m2etot;
    g_m2i[m]   = m2ip_m;
    g_i2i[m]   = i2ip_m;
    g_asc[m]   = (m >= 1) ? dtdp_m1 : 1.f;
    g_msc[m]   = mtdp_m;

    {
        const float* row = em_kernel + m * 25;
        float mxr = row[0];
        for (int s = 1; s < 25; s++) mxr = fmaxf(mxr, row[s]);
        float z = 0.f;
        for (int s = 0; s < 25; s++) z += expf(row[s] - mxr);
        float invz = 1.f / z;
        for (int s = 0; s < 25; s++) g_em[s * 512 + m] = expf(row[s] - mxr) * invz;
    }
    if (m == 0) {
        float mxi = ins_kernel[0];
        for (int s = 1; s < 25; s++) mxi = fmaxf(mxi, ins_kernel[s]);
        float z = 0.f;
        for (int s = 0; s < 25; s++) z += expf(ins_kernel[s] - mxi);
        for (int s = 0; s < 25; s++) g_insd[s] = expf(ins_kernel[s] - mxi) / z;
        float a = lf_loop[0], b = lf_exit[0], mx = fmaxf(a, b);
        float ea = expf(a-mx), eb = expf(b-mx), z2 = ea+eb;
        float u = e2u[0], r = e2r[0], t = e2t[0];
        float mxe = fmaxf(fmaxf(u, r), t);
        float eu = expf(u-mxe), er = expf(r-mxe), et = expf(t-mxe);
        float ze = eu + er + et;
        g_scal[0] = ea/z2;  // floop
        g_scal[1] = eb/z2;  // fexit
        g_scal[2] = be;
        g_scal[3] = eu/ze;  // ep0
        g_scal[4] = er/ze;  // ep1
        g_scal[5] = 1.f / (1.f + expf(-flank_kernel[0]));  // p0
    }
}

// ---------------- forward kernel: 1 CTA per batch, 64 threads, 2 warps ------
struct Buf {
    float wB0, mx[2], tot[2];
    float nbM[3], nbI[3];
};

__global__ __launch_bounds__(64, 1)
void fwd_kernel(const int* __restrict__ seq, float* __restrict__ out)
{
    __shared__ int   s_seq[1024];
    __shared__ float s_insd[32];
    __shared__ Buf   s_b[2];
    __shared__ float s_ftot[2];

    const int tid = threadIdx.x, lane = tid & 31, warp = tid >> 5;
    const int b = blockIdx.x;
    const int m0 = tid * 8;
    const unsigned FULL = 0xffffffffu;

    // stage sequence + insert dist + boundary zeros
    {
        const int4* sp = (const int4*)(seq + b * 1024);
        #pragma unroll
        for (int k = 0; k < 4; k++)
            ((int4*)s_seq)[tid + 64 * k] = sp[tid + 64 * k];
        if (tid < 25) s_insd[tid] = g_insd[tid];
        if (tid < 2) { s_b[tid].nbM[0] = 0.f; s_b[tid].nbI[0] = 0.f; }
    }

    // per-thread constants (8 states each)
    float en[8], mtc[8], i2mc[8], mec[8], mic[8], iic[8], asc[8], msc[8], dtc[8];
    {
        #pragma unroll
        for (int h = 0; h < 2; h++) {
            int o = m0 + 4 * h;
            float4 v;
            v = *(const float4*)(g_enter + o); en[4*h]=v.x; en[4*h+1]=v.y; en[4*h+2]=v.z; en[4*h+3]=v.w;
            v = *(const float4*)(g_mtm   + o); mtc[4*h]=v.x; mtc[4*h+1]=v.y; mtc[4*h+2]=v.z; mtc[4*h+3]=v.w;
            v = *(const float4*)(g_i2m   + o); i2mc[4*h]=v.x; i2mc[4*h+1]=v.y; i2mc[4*h+2]=v.z; i2mc[4*h+3]=v.w;
            v = *(const float4*)(g_dtm   + o); dtc[4*h]=v.x; dtc[4*h+1]=v.y; dtc[4*h+2]=v.z; dtc[4*h+3]=v.w;
            v = *(const float4*)(g_m2e   + o); mec[4*h]=v.x; mec[4*h+1]=v.y; mec[4*h+2]=v.z; mec[4*h+3]=v.w;
            v = *(const float4*)(g_m2i   + o); mic[4*h]=v.x; mic[4*h+1]=v.y; mic[4*h+2]=v.z; mic[4*h+3]=v.w;
            v = *(const float4*)(g_i2i   + o); iic[4*h]=v.x; iic[4*h+1]=v.y; iic[4*h+2]=v.z; iic[4*h+3]=v.w;
            v = *(const float4*)(g_asc   + o); asc[4*h]=v.x; asc[4*h+1]=v.y; asc[4*h+2]=v.z; asc[4*h+3]=v.w;
            v = *(const float4*)(g_msc   + o); msc[4*h]=v.x; msc[4*h+1]=v.y; msc[4*h+2]=v.z; msc[4*h+3]=v.w;
        }
    }
    // scaled-prefix constants:
    // P[k] = prod asc[0..k];  mscP[k] = msc[k]/P[k];  dtcP[k] = dtc[k]*PA(k) (PA(k)=P[k-1], PA(0)=1)
    // dpm[k] = dtcP[k]*mscP[0] (k>=1)
    float P[8];
    P[0] = asc[0];
    #pragma unroll
    for (int k = 1; k < 8; k++) P[k] = P[k-1] * asc[k];
    float mscP[8], dtcP[8], dpm[8];
    #pragma unroll
    for (int k = 0; k < 8; k++) mscP[k] = msc[k] / P[k];
    dtcP[0] = dtc[0];
    #pragma unroll
    for (int k = 1; k < 8; k++) dtcP[k] = dtc[k] * P[k-1];
    dpm[0] = 0.f;
    #pragma unroll
    for (int k = 1; k < 8; k++) dpm[k] = dtcP[k] * mscP[0];
    const float segA = P[7];
    const float cU   = P[7];             // iB = cU*u'' + cPm*prevM
    const float cPm  = P[7] * mscP[0];

    const float floop = g_scal[0], fexit = g_scal[1], be = g_scal[2];
    const float ep0 = g_scal[3], ep1 = g_scal[4], p0 = g_scal[5];
    const float fbe0 = fexit * be * ep0, fbe1 = fexit * be * ep1;
    const float Kown = (warp == 1) ? (g_msc[256] / g_asc[256]) : 0.f;

    // prolog: radix-4 scan constants on the SHIFTED per-lane A (As_j = segA_{j-1})
    float c11, c12, c13, c21, c22, c23, c31, eAc;
    {
        float As = __shfl_up_sync(FULL, segA, 1);
        if (lane == 0) As = 1.f;
        float a1 = __shfl_up_sync(FULL, As, 1);
        float a2 = __shfl_up_sync(FULL, As, 2);
        float a3 = __shfl_up_sync(FULL, As, 3);
        c11 = (lane >= 1) ? As : 0.f;
        c12 = (lane >= 2) ? As * a1 : 0.f;
        c13 = (lane >= 3) ? As * a1 * a2 : 0.f;
        float G1 = As;
        if (lane >= 1) G1 *= a1;
        if (lane >= 2) G1 *= a2;
        if (lane >= 3) G1 *= a3;
        float g1 = __shfl_up_sync(FULL, G1, 4);
        float g2 = __shfl_up_sync(FULL, G1, 8);
        float g3 = __shfl_up_sync(FULL, G1, 12);
        c21 = (lane >= 4)  ? G1 : 0.f;
        c22 = (lane >= 8)  ? G1 * g1 : 0.f;
        c23 = (lane >= 12) ? G1 * g1 * g2 : 0.f;
        float G2 = G1;
        if (lane >= 4)  G2 *= g1;
        if (lane >= 8)  G2 *= g2;
        if (lane >= 12) G2 *= g3;
        c31 = (lane >= 16) ? G2 : 0.f;
        float h1 = __shfl_up_sync(FULL, G2, 16);
        float G3 = G2;
        if (lane >= 16) G3 *= h1;
        eAc = G3;   // prod of original A over lanes < me (within warp)
    }
    __syncthreads();

    // ---- t = 0 init ----
    int c = s_seq[0];
    float eins = s_insd[c];
    float aM[8], aI[8], em[8];
    {
        float4 ea = __ldg((const float4*)(g_em + c * 512 + m0));
        float4 eb = __ldg((const float4*)(g_em + c * 512 + m0 + 4));
        em[0]=ea.x; em[1]=ea.y; em[2]=ea.z; em[3]=ea.w;
        em[4]=eb.x; em[5]=eb.y; em[6]=eb.z; em[7]=eb.w;
    }
    const float q0 = 1.f - p0;
    #pragma unroll
    for (int k = 0; k < 8; k++) { aM[k] = q0 * en[k] * em[k]; aI[k] = 0.f; }
    float aLF = p0 * eins, aU = q0 * be * ep0 * eins, aRF = q0 * be * ep1 * eins;
    float ll;
    {
        float tp = 0.f;
        #pragma unroll
        for (int k = 0; k < 8; k++) tp += aM[k];
        #pragma unroll
        for (int d = 16; d; d >>= 1) tp += __shfl_xor_sync(FULL, tp, d);
        if (lane == 0) s_ftot[warp] = tp;
        __syncthreads();
        float s = s_ftot[0] + s_ftot[1] + aLF + aU + aRF + TINYF;
        float inv = 1.f / s; ll = logf(s);
        #pragma unroll
        for (int k = 0; k < 8; k++) aM[k] *= inv;
        aLF *= inv; aU *= inv; aRF *= inv;
        __syncthreads();
    }

    // ---- main recurrence: 1 barrier per step, rescale every 16 steps ----
    #pragma unroll 2
    for (int t = 1; t < 1024; t++) {
        Buf* bf = &s_b[t & 1];
        const bool rescale = ((t & 15) == 0);

        c = s_seq[t];
        eins = s_insd[c];
        {
            float4 ea = __ldg((const float4*)(g_em + c * 512 + m0));
            float4 eb = __ldg((const float4*)(g_em + c * 512 + m0 + 4));
            em[0]=ea.x; em[1]=ea.y; em[2]=ea.z; em[3]=ea.w;
            em[4]=eb.x; em[5]=eb.y; em[6]=eb.z; em[7]=eb.w;
        }

        // ---- phase A ----
        if (lane == 31) {  // neighbor handoff: available immediately
            bf->nbM[warp + 1] = aM[7]; bf->nbI[warp + 1] = aI[7];
        }
        float prevM = __shfl_up_sync(FULL, aM[7], 1);
        float prevI = __shfl_up_sync(FULL, aI[7], 1);
        if (lane == 0) { prevM = 0.f; prevI = 0.f; }

        const float fc = fexit * (aLF + aU);

        // pre[k] and scaled running sum u'' (u2). pre[k] uses u''(k) BEFORE adding term k.
        float pre[8];
        pre[0] = fmaf(i2mc[0], prevI, fmaf(mtc[0], prevM, en[0]*fc));
        float u2 = 0.f;
        #pragma unroll
        for (int k = 1; k < 8; k++) {
            pre[k] = fmaf(dtcP[k], u2,
                     fmaf(dpm[k], prevM,
                     fmaf(i2mc[k], aI[k-1],
                     fmaf(mtc[k], aM[k-1], en[k]*fc))));
            u2 = fmaf(aM[k-1], mscP[k], u2);
        }
        float iB = fmaf(prevM, cPm, u2 * cU);   // full segment sum (unshifted)

        // mexit dot + butterfly (off critical path)
        float mx = 0.f;
        #pragma unroll
        for (int k = 0; k < 8; k++) mx = fmaf(mec[k], aM[k], mx);
        #pragma unroll
        for (int d = 16; d; d >>= 1) mx += __shfl_xor_sync(FULL, mx, d);

        float tp = 0.f;
        if (rescale) {
            #pragma unroll
            for (int k = 0; k < 8; k++) tp += aM[k] + aI[k];
            #pragma unroll
            for (int d = 16; d; d >>= 1) tp += __shfl_xor_sync(FULL, tp, d);
        }

        // ---- shifted radix-4 scan -> exclusive prefix ----
        float x = __shfl_up_sync(FULL, iB, 1);
        if (lane == 0) x = 0.f;
        {
            float x1 = __shfl_up_sync(FULL, x, 1);
            float x2 = __shfl_up_sync(FULL, x, 2);
            float x3 = __shfl_up_sync(FULL, x, 3);
            x = fmaf(x3, c13, fmaf(x2, c12, fmaf(x1, c11, x)));
            x1 = __shfl_up_sync(FULL, x, 4);
            x2 = __shfl_up_sync(FULL, x, 8);
            x3 = __shfl_up_sync(FULL, x, 12);
            x = fmaf(x3, c23, fmaf(x2, c22, fmaf(x1, c21, x)));
            x1 = __shfl_up_sync(FULL, x, 16);
            x = fmaf(x1, c31, x);
        }
        const float excl = x;   // prefix over lanes < me (within warp)

        if (warp == 0 && lane == 31)
            bf->wB0 = fmaf(excl, segA, iB);   // warp-0 total
        if (lane == 0) {
            bf->mx[warp] = mx;
            if (rescale) bf->tot[warp] = tp;
        }
        __syncthreads();   // the single barrier

        // ---- phase B ----
        const float pB    = (warp == 1) ? bf->wB0 : 0.f;
        const float nbOwn = bf->nbM[warp];
        const float nbIv  = bf->nbI[warp];
        const float base  = fmaf(nbOwn, Kown, pB);
        float v_in = fmaf(eAc, base, excl);
        float wk0  = v_in;
        if (lane == 0) {
            v_in = base;
            wk0  = pB;
            pre[0] = fmaf(mtc[0], nbOwn, fmaf(i2mc[0], nbIv, pre[0]));
        }

        float nM[8], nI[8];
        nM[0] = em[0] * fmaf(dtcP[0], wk0, pre[0]);
        #pragma unroll
        for (int k = 1; k < 8; k++)
            nM[k] = em[k] * fmaf(dtcP[k], v_in, pre[k]);
        #pragma unroll
        for (int k = 0; k < 8; k++)
            nI[k] = eins * fmaf(mic[k], aM[k], iic[k] * aI[k]);

        const float mexit = bf->mx[0] + bf->mx[1];
        float nLF = eins * floop * aLF;
        float nU  = eins * (fmaf(ep0, mexit, fbe0 * aLF) + (floop + fbe0) * aU);
        float nRF = eins * (fmaf(ep1, mexit, fbe1 * (aLF + aU)) + floop * aRF);

        if (rescale) {
            float s = bf->tot[0] + bf->tot[1] + aLF + aU + aRF + TINYF;
            float inv = 1.f / s;
            ll += logf(s);
            #pragma unroll
            for (int k = 0; k < 8; k++) { nM[k] *= inv; nI[k] *= inv; }
            nLF *= inv; nU *= inv; nRF *= inv;
        }

        #pragma unroll
        for (int k = 0; k < 8; k++) { aM[k] = nM[k]; aI[k] = nI[k]; }
        aLF = nLF; aU = nU; aRF = nRF;
    }

    // ---- final mass -> log-likelihood ----
    {
        float tp = 0.f;
        #pragma unroll
        for (int k = 0; k < 8; k++) tp += aM[k] + aI[k];
        #pragma unroll
        for (int d = 16; d; d >>= 1) tp += __shfl_xor_sync(FULL, tp, d);
        __syncthreads();
        if (lane == 0) s_ftot[warp] = tp;
        __syncthreads();
        float s = s_ftot[0] + s_ftot[1] + aLF + aU + aRF + TINYF;
        ll += logf(s);
        if (tid == 0) out[b] = ll;
    }
}

extern "C" void kernel_launch(void* const* d_in, const int* in_sizes, int n_in,
                              void* d_out, int out_size)
{
    setup_kernel<<<1, 512>>>(
        (const float*)d_in[1],  (const float*)d_in[2],  (const float*)d_in[3],
        (const float*)d_in[4],  (const float*)d_in[5],  (const float*)d_in[6],
        (const float*)d_in[7],  (const float*)d_in[8],  (const float*)d_in[9],
        (const float*)d_in[10], (const float*)d_in[11], (const float*)d_in[12],
        (const float*)d_in[13], (const float*)d_in[14], (const float*)d_in[15],
        (const float*)d_in[16], (const float*)d_in[17]);
    fwd_kernel<<<128, 64>>>((const int*)d_in[0], (float*)d_out);
}